// round 8
// baseline (speedup 1.0000x reference)
#include <cuda_runtime.h>
#include <math.h>
#include <stdint.h>

#define BB 2
#define SS 2048
#define HH 1024
#define NH 16
#define DD 64

// Scratch: Q/K/V and attention output stored as tf32 BITS (uint32)
__device__ uint32_t g_Q[(size_t)BB * NH * SS * DD];
__device__ uint32_t g_K[(size_t)BB * NH * SS * DD];
__device__ uint32_t g_V[(size_t)BB * NH * SS * DD];
__device__ uint32_t g_Ac[(size_t)BB * SS * HH];
__device__ uint32_t g_Xqc[(size_t)BB * SS * HH];
__device__ uint32_t g_Xsc[(size_t)BB * SS * HH];
__device__ uint32_t g_Wc[(size_t)10 * HH * HH];  // Wq(3) Wk(3) Wv(3) Wo(1), [k][n]

// ---------------------------------------------------------------------------
__device__ __forceinline__ uint32_t f2tf32(float x) {
    uint32_t r;
    asm("cvt.rna.tf32.f32 %0, %1;" : "=r"(r) : "f"(x));
    return r;
}
__device__ __forceinline__ void mma_tf32(float* d, const uint32_t* a, const uint32_t* b) {
    asm volatile(
        "mma.sync.aligned.m16n8k8.row.col.f32.tf32.tf32.f32 "
        "{%0,%1,%2,%3}, {%4,%5,%6,%7}, {%8,%9}, {%0,%1,%2,%3};"
        : "+f"(d[0]), "+f"(d[1]), "+f"(d[2]), "+f"(d[3])
        : "r"(a[0]), "r"(a[1]), "r"(a[2]), "r"(a[3]), "r"(b[0]), "r"(b[1]));
}
__device__ __forceinline__ uint32_t smem_u32(const void* p) {
    uint32_t a;
    asm("{ .reg .u64 t; cvta.to.shared.u64 t, %1; cvt.u32.u64 %0, t; }" : "=r"(a) : "l"(p));
    return a;
}
#define CP_ASYNC(dst, src, sz) \
    asm volatile("cp.async.cg.shared.global [%0], [%1], 16, %2;" \
                 :: "r"(dst), "l"(src), "r"(sz) : "memory")
#define CP_COMMIT() asm volatile("cp.async.commit_group;" ::: "memory")
#define CP_WAIT1()  asm volatile("cp.async.wait_group 1;" ::: "memory")

// ---------------------------------------------------------------------------
// Pre-conversion kernels (fp32 -> tf32 bits)
// ---------------------------------------------------------------------------
__global__ __launch_bounds__(256) void cvt4(const float* __restrict__ x,
                                            uint32_t* __restrict__ y, int n4)
{
    int i = blockIdx.x * 256 + threadIdx.x;
    if (i < n4) {
        float4 v = ((const float4*)x)[i];
        uint4 u;
        u.x = f2tf32(v.x); u.y = f2tf32(v.y);
        u.z = f2tf32(v.z); u.w = f2tf32(v.w);
        ((uint4*)y)[i] = u;
    }
}
__global__ __launch_bounds__(256) void cvt_w(
    const float* __restrict__ Wq, const float* __restrict__ Wk,
    const float* __restrict__ Wv, const float* __restrict__ Wo,
    uint32_t* __restrict__ y)
{
    int z = blockIdx.z;
    const float* src = z < 3 ? Wq + (size_t)z * HH * HH
                     : z < 6 ? Wk + (size_t)(z - 3) * HH * HH
                     : z < 9 ? Wv + (size_t)(z - 6) * HH * HH
                             : Wo;
    uint32_t* dst = y + (size_t)z * HH * HH;
    int i = blockIdx.x * 256 + threadIdx.x;
    float4 v = ((const float4*)src)[i];
    uint4 u;
    u.x = f2tf32(v.x); u.y = f2tf32(v.y);
    u.z = f2tf32(v.z); u.w = f2tf32(v.w);
    ((uint4*)dst)[i] = u;
}

// ---------------------------------------------------------------------------
// cp.async 3-stage BK=32 tf32 mma GEMM with conv halo. ONE sync per k-chunk.
// BM=BN=128, 256 threads = 8 warps (2m x 4n), warp tile 64x32.
// A smem [m][k] stride 36 (frag bank = 4g+tg+8ks: conflict-free).
// B smem [k][n] stride 128, XOR swizzle n ^ ((k&3)<<3) (conflict-free).
// Accumulation order identical to rounds 4-7: bit-identical results.
// ---------------------------------------------------------------------------
#define A_STRIDE 36
#define A_WORDS (128 * A_STRIDE)       // 4608
#define STG_WORDS (A_WORDS + 32 * 128) // 8704
#define STG_BYTES (STG_WORDS * 4)      // 34816
#define GEMM_DSMEM (3 * STG_BYTES)     // 104448

template <int TAPS, bool HEADS_OUT>
__device__ __forceinline__ void gemm_ca_core(
    const uint32_t* __restrict__ Xc, const uint32_t* __restrict__ Wc,
    const float* __restrict__ bias, void* __restrict__ Yv_, float scale,
    int m0, int n0)
{
    extern __shared__ uint32_t sm[];
    const uint32_t smb = smem_u32(sm);

    const int tid = threadIdx.x;
    const int wid = tid >> 5;
    const int lane = tid & 31;
    const int g = lane >> 2;
    const int tg = lane & 3;
    const int wm = wid >> 2;
    const int wn = wid & 3;
    const int batch = m0 >> 11;
    const int tb = m0 & (SS - 1);
    const int CENTER = (TAPS - 1) / 2;
    const int NIT = TAPS * 32;             // 32 k-chunks of 32 per tap

    // staging coords: 4 chunks per operand per thread
    int am[4], ak4[4], bk[4], bn4[4];
#pragma unroll
    for (int p = 0; p < 4; ++p) {
        int f = tid + p * 256;
        am[p] = f >> 3;
        ak4[p] = (f & 7) << 2;
        bk[p] = f >> 5;
        bn4[p] = (f & 31) << 2;
    }

    auto issue = [&](int it) {
        const int tap = it >> 5;
        const int c0 = (it & 31) << 5;
        const uint32_t sb = smb + (uint32_t)(it % 3) * STG_BYTES;
        const uint32_t* wt = Wc + (size_t)tap * HH * HH;
#pragma unroll
        for (int p = 0; p < 4; ++p) {
            int srow = tb + am[p] + tap - CENTER;
            uint32_t sz = 16;
            int sr = srow;
            if (TAPS > 1) {
                sz = (srow >= 0 && srow < SS) ? 16u : 0u;
                sr = srow < 0 ? 0 : (srow >= SS ? SS - 1 : srow);
            }
            const uint32_t* srcA = Xc + ((size_t)batch * SS + sr) * HH + c0 + ak4[p];
            CP_ASYNC(sb + (uint32_t)(am[p] * A_STRIDE + ak4[p]) * 4, srcA, sz);
            const uint32_t* srcB = wt + (size_t)(c0 + bk[p]) * HH + n0 + bn4[p];
            uint32_t swz = (uint32_t)(bn4[p] ^ ((bk[p] & 3) << 3));
            CP_ASYNC(sb + (A_WORDS + (uint32_t)bk[p] * 128 + swz) * 4, srcB, 16u);
        }
    };

    float acc[4][4][4];
#pragma unroll
    for (int i = 0; i < 4; ++i)
#pragma unroll
        for (int j = 0; j < 4; ++j)
#pragma unroll
            for (int r = 0; r < 4; ++r) acc[i][j][r] = 0.f;

    issue(0); CP_COMMIT();
    issue(1); CP_COMMIT();

    for (int it = 0; it < NIT; ++it) {
        CP_WAIT1();
        __syncthreads();
        if (it + 2 < NIT) issue(it + 2);
        CP_COMMIT();

        const uint32_t* sA = sm + (it % 3) * STG_WORDS;
        const uint32_t* sB = sA + A_WORDS;
#pragma unroll
        for (int ks = 0; ks < 4; ++ks) {
            const int k1 = ks * 8 + tg;
            const int k2 = k1 + 4;
            uint32_t a[4][4], b[4][2];
#pragma unroll
            for (int mt = 0; mt < 4; ++mt) {
                int mr = wm * 64 + mt * 16 + g;
                a[mt][0] = sA[mr * A_STRIDE + k1];
                a[mt][1] = sA[(mr + 8) * A_STRIDE + k1];
                a[mt][2] = sA[mr * A_STRIDE + k2];
                a[mt][3] = sA[(mr + 8) * A_STRIDE + k2];
            }
#pragma unroll
            for (int nt = 0; nt < 4; ++nt) {
                int ncx = (wn * 32 + nt * 8 + g) ^ (tg << 3);
                b[nt][0] = sB[k1 * 128 + ncx];
                b[nt][1] = sB[k2 * 128 + ncx];
            }
#pragma unroll
            for (int mt = 0; mt < 4; ++mt)
#pragma unroll
                for (int nt = 0; nt < 4; ++nt)
                    mma_tf32(acc[mt][nt], a[mt], b[nt]);
        }
    }

    // epilogue
#pragma unroll
    for (int mt = 0; mt < 4; ++mt)
#pragma unroll
        for (int half = 0; half < 2; ++half) {
            int m = m0 + wm * 64 + mt * 16 + g + half * 8;
            int bidx = m >> 11;
            int t = m & (SS - 1);
#pragma unroll
            for (int nt = 0; nt < 4; ++nt) {
                int n = n0 + wn * 32 + nt * 8 + tg * 2;
                float ox = (acc[mt][nt][half * 2 + 0] + bias[n + 0]) * scale;
                float oy = (acc[mt][nt][half * 2 + 1] + bias[n + 1]) * scale;
                if (HEADS_OUT) {
                    // store tf32 bits in split-head layout
                    int h = n >> 6, d = n & 63;
                    uint2 u;
                    u.x = f2tf32(ox);
                    u.y = f2tf32(oy);
                    *(uint2*)((uint32_t*)Yv_ +
                              (((size_t)bidx * NH + h) * SS + t) * DD + d) = u;
                } else {
                    float2 o = make_float2(ox, oy);
                    *(float2*)((float*)Yv_ + (size_t)m * HH + n) = o;
                }
            }
        }
}

__global__ __launch_bounds__(256, 2) void conv3_ca(
    const uint32_t* __restrict__ Xq, const uint32_t* __restrict__ Xs,
    const uint32_t* __restrict__ Wc,
    const float* __restrict__ bq, const float* __restrict__ bk,
    const float* __restrict__ bv,
    uint32_t* __restrict__ Yq, uint32_t* __restrict__ Yk,
    uint32_t* __restrict__ Yv)
{
    const int z = blockIdx.z;
    gemm_ca_core<3, true>(z ? Xs : Xq, Wc + (size_t)z * 3 * HH * HH,
                          z == 0 ? bq : (z == 1 ? bk : bv),
                          z == 0 ? Yq : (z == 1 ? Yk : Yv),
                          z == 0 ? 0.125f : 1.0f,
                          blockIdx.y * 128, blockIdx.x * 128);
}

__global__ __launch_bounds__(256, 2) void outproj_ca(
    const uint32_t* __restrict__ Xc, const uint32_t* __restrict__ Wc,
    const float* __restrict__ bias, float* __restrict__ Y)
{
    gemm_ca_core<1, false>(Xc, Wc + (size_t)9 * HH * HH, bias, Y, 1.0f,
                           blockIdx.y * 128, blockIdx.x * 128);
}

// ---------------------------------------------------------------------------
// Tensor-core flash attention. Q/K/V arrive as tf32 bits (pure-copy staging).
// Writes tf32 bits of the normalized output directly (feeds outproj).
// ---------------------------------------------------------------------------
__global__ __launch_bounds__(256) void attn_tc(const float* __restrict__ mask,
                                               uint32_t* __restrict__ Aout)
{
    __shared__ uint32_t Kn[64][76];
    __shared__ uint32_t Vs[64][72];
    __shared__ float msk[SS];

    const int q0 = blockIdx.x * 128;
    const int h = blockIdx.y;
    const int b = blockIdx.z;
    const int tid = threadIdx.x;
    const int wid = tid >> 5;
    const int lane = tid & 31;
    const int g = lane >> 2;
    const int tg = lane & 3;
    const size_t base = ((size_t)b * NH + h) * SS * DD;
    const int qr = q0 + wid * 16;

    for (int i = tid; i < SS; i += 256)
        msk[i] = mask[(size_t)b * SS + i] * (-1e9f);

    uint32_t qa[8][4];
    {
        const uint32_t* Qp = g_Q + base + (size_t)(qr + g) * DD + tg;
#pragma unroll
        for (int ks = 0; ks < 8; ++ks) {
            qa[ks][0] = Qp[ks * 8];
            qa[ks][1] = Qp[ks * 8 + 8 * DD];
            qa[ks][2] = Qp[ks * 8 + 4];
            qa[ks][3] = Qp[ks * 8 + 4 + 8 * DD];
        }
    }

    float oacc[8][4];
#pragma unroll
    for (int nt = 0; nt < 8; ++nt)
#pragma unroll
        for (int r = 0; r < 4; ++r) oacc[nt][r] = 0.f;
    float m0 = -1e30f, m8 = -1e30f, l0 = 0.f, l8 = 0.f;

    for (int k0 = 0; k0 < SS; k0 += 64) {
        __syncthreads();
#pragma unroll
        for (int p = 0; p < 4; ++p) {
            int f = tid + p * 256;
            int r = f >> 4;
            int c4 = (f & 15) << 2;
            uint4 kv = *(const uint4*)(g_K + base + (size_t)(k0 + r) * DD + c4);
            uint4 vv = *(const uint4*)(g_V + base + (size_t)(k0 + r) * DD + c4);
            *(uint4*)&Kn[r][c4] = kv;
            *(uint4*)&Vs[r][c4] = vv;
        }
        __syncthreads();

        float sacc[8][4];
#pragma unroll
        for (int nt = 0; nt < 8; ++nt)
#pragma unroll
            for (int r = 0; r < 4; ++r) sacc[nt][r] = 0.f;
#pragma unroll
        for (int ks = 0; ks < 8; ++ks)
#pragma unroll
            for (int nt = 0; nt < 8; ++nt) {
                uint32_t bfr[2];
                bfr[0] = Kn[nt * 8 + g][ks * 8 + tg];
                bfr[1] = Kn[nt * 8 + g][ks * 8 + tg + 4];
                mma_tf32(sacc[nt], qa[ks], bfr);
            }

#pragma unroll
        for (int nt = 0; nt < 8; ++nt) {
            float mk0 = msk[k0 + nt * 8 + 2 * tg];
            float mk1 = msk[k0 + nt * 8 + 2 * tg + 1];
            sacc[nt][0] += mk0; sacc[nt][1] += mk1;
            sacc[nt][2] += mk0; sacc[nt][3] += mk1;
        }

        float r0 = -1e30f, r8 = -1e30f;
#pragma unroll
        for (int nt = 0; nt < 8; ++nt) {
            r0 = fmaxf(r0, fmaxf(sacc[nt][0], sacc[nt][1]));
            r8 = fmaxf(r8, fmaxf(sacc[nt][2], sacc[nt][3]));
        }
        r0 = fmaxf(r0, __shfl_xor_sync(0xffffffffu, r0, 1));
        r0 = fmaxf(r0, __shfl_xor_sync(0xffffffffu, r0, 2));
        r8 = fmaxf(r8, __shfl_xor_sync(0xffffffffu, r8, 1));
        r8 = fmaxf(r8, __shfl_xor_sync(0xffffffffu, r8, 2));

        float nm0 = fmaxf(m0, r0), nm8 = fmaxf(m8, r8);
        float cr0 = __expf(m0 - nm0), cr8 = __expf(m8 - nm8);

        float s0 = 0.f, s8 = 0.f;
#pragma unroll
        for (int nt = 0; nt < 8; ++nt) {
            sacc[nt][0] = __expf(sacc[nt][0] - nm0);
            sacc[nt][1] = __expf(sacc[nt][1] - nm0);
            sacc[nt][2] = __expf(sacc[nt][2] - nm8);
            sacc[nt][3] = __expf(sacc[nt][3] - nm8);
            s0 += sacc[nt][0] + sacc[nt][1];
            s8 += sacc[nt][2] + sacc[nt][3];
        }
        s0 += __shfl_xor_sync(0xffffffffu, s0, 1);
        s0 += __shfl_xor_sync(0xffffffffu, s0, 2);
        s8 += __shfl_xor_sync(0xffffffffu, s8, 1);
        s8 += __shfl_xor_sync(0xffffffffu, s8, 2);

        l0 = l0 * cr0 + s0;
        l8 = l8 * cr8 + s8;
        m0 = nm0; m8 = nm8;

#pragma unroll
        for (int nt = 0; nt < 8; ++nt) {
            oacc[nt][0] *= cr0; oacc[nt][1] *= cr0;
            oacc[nt][2] *= cr8; oacc[nt][3] *= cr8;
        }

        const int src0 = (g << 2) + (tg >> 1);
        const int src2 = src0 + 2;
        const bool odd = tg & 1;
#pragma unroll
        for (int ks = 0; ks < 8; ++ks) {
            float e00 = __shfl_sync(0xffffffffu, sacc[ks][0], src0);
            float e01 = __shfl_sync(0xffffffffu, sacc[ks][1], src0);
            float e10 = __shfl_sync(0xffffffffu, sacc[ks][2], src0);
            float e11 = __shfl_sync(0xffffffffu, sacc[ks][3], src0);
            float e20 = __shfl_sync(0xffffffffu, sacc[ks][0], src2);
            float e21 = __shfl_sync(0xffffffffu, sacc[ks][1], src2);
            float e30 = __shfl_sync(0xffffffffu, sacc[ks][2], src2);
            float e31 = __shfl_sync(0xffffffffu, sacc[ks][3], src2);
            uint32_t pa[4];
            pa[0] = f2tf32(odd ? e01 : e00);
            pa[1] = f2tf32(odd ? e11 : e10);
            pa[2] = f2tf32(odd ? e21 : e20);
            pa[3] = f2tf32(odd ? e31 : e30);
#pragma unroll
            for (int nt = 0; nt < 8; ++nt) {
                uint32_t bfr[2];
                bfr[0] = Vs[ks * 8 + tg][nt * 8 + g];
                bfr[1] = Vs[ks * 8 + tg + 4][nt * 8 + g];
                mma_tf32(oacc[nt], pa, bfr);
            }
        }
    }

    const float inv0 = 1.f / l0, inv8 = 1.f / l8;
#pragma unroll
    for (int nt = 0; nt < 8; ++nt) {
        uint2 o0, o8;
        o0.x = f2tf32(oacc[nt][0] * inv0); o0.y = f2tf32(oacc[nt][1] * inv0);
        o8.x = f2tf32(oacc[nt][2] * inv8); o8.y = f2tf32(oacc[nt][3] * inv8);
        size_t col = (size_t)h * DD + nt * 8 + 2 * tg;
        *(uint2*)(Aout + ((size_t)b * SS + qr + g) * HH + col) = o0;
        *(uint2*)(Aout + ((size_t)b * SS + qr + g + 8) * HH + col) = o8;
    }
}

// ---------------------------------------------------------------------------
extern "C" void kernel_launch(void* const* d_in, const int* in_sizes, int n_in,
                              void* d_out, int out_size)
{
    const float* qin  = (const float*)d_in[0];
    const float* src  = (const float*)d_in[1];
    const float* mask = (const float*)d_in[2];
    const float* Wq   = (const float*)d_in[3];
    const float* bq   = (const float*)d_in[4];
    const float* Wk   = (const float*)d_in[5];
    const float* bk   = (const float*)d_in[6];
    const float* Wv   = (const float*)d_in[7];
    const float* bv   = (const float*)d_in[8];
    const float* Wo   = (const float*)d_in[9];
    const float* bo   = (const float*)d_in[10];
    float* out = (float*)d_out;

    uint32_t *gQ, *gK, *gV, *gAc, *gXq, *gXs, *gW;
    cudaGetSymbolAddress((void**)&gQ, g_Q);
    cudaGetSymbolAddress((void**)&gK, g_K);
    cudaGetSymbolAddress((void**)&gV, g_V);
    cudaGetSymbolAddress((void**)&gAc, g_Ac);
    cudaGetSymbolAddress((void**)&gXq, g_Xqc);
    cudaGetSymbolAddress((void**)&gXs, g_Xsc);
    cudaGetSymbolAddress((void**)&gW, g_Wc);

    cudaFuncSetAttribute(conv3_ca, cudaFuncAttributeMaxDynamicSharedMemorySize,
                         GEMM_DSMEM);
    cudaFuncSetAttribute(outproj_ca, cudaFuncAttributeMaxDynamicSharedMemorySize,
                         GEMM_DSMEM);

    const int N4 = BB * SS * HH / 4;
    cvt4<<<(N4 + 255) / 256, 256>>>(qin, gXq, N4);
    cvt4<<<(N4 + 255) / 256, 256>>>(src, gXs, N4);
    dim3 gridW(HH * HH / 4 / 256, 1, 10);
    cvt_w<<<gridW, 256>>>(Wq, Wk, Wv, Wo, gW);

    dim3 gridC(HH / 128, (BB * SS) / 128, 3);
    conv3_ca<<<gridC, 256, GEMM_DSMEM>>>(gXq, gXs, gW, bq, bk, bv, gQ, gK, gV);

    dim3 gridAttn(SS / 128, NH, BB);
    attn_tc<<<gridAttn, 256>>>(mask, gAc);

    dim3 gridO(HH / 128, (BB * SS) / 128);
    outproj_ca<<<gridO, 256, GEMM_DSMEM>>>(gAc, gW, bo, out);
}

// round 9
// speedup vs baseline: 1.0316x; 1.0316x over previous
#include <cuda_runtime.h>
#include <math.h>
#include <stdint.h>

#define BB 2
#define SS 2048
#define HH 1024
#define NH 16
#define DD 64

// Scratch: Q/K/V and attention output stored as tf32 BITS (uint32)
__device__ uint32_t g_Q[(size_t)BB * NH * SS * DD];
__device__ uint32_t g_K[(size_t)BB * NH * SS * DD];
__device__ uint32_t g_V[(size_t)BB * NH * SS * DD];
__device__ uint32_t g_Ac[(size_t)BB * SS * HH];
__device__ uint32_t g_Xqc[(size_t)BB * SS * HH];
__device__ uint32_t g_Xsc[(size_t)BB * SS * HH];
__device__ uint32_t g_Wc[(size_t)10 * HH * HH];  // Wq(3) Wk(3) Wv(3) Wo(1), [k][n]

// ---------------------------------------------------------------------------
__device__ __forceinline__ uint32_t f2tf32(float x) {
    uint32_t r;
    asm("cvt.rna.tf32.f32 %0, %1;" : "=r"(r) : "f"(x));
    return r;
}
__device__ __forceinline__ void mma_tf32(float* d, const uint32_t* a, const uint32_t* b) {
    asm volatile(
        "mma.sync.aligned.m16n8k8.row.col.f32.tf32.tf32.f32 "
        "{%0,%1,%2,%3}, {%4,%5,%6,%7}, {%8,%9}, {%0,%1,%2,%3};"
        : "+f"(d[0]), "+f"(d[1]), "+f"(d[2]), "+f"(d[3])
        : "r"(a[0]), "r"(a[1]), "r"(a[2]), "r"(a[3]), "r"(b[0]), "r"(b[1]));
}
__device__ __forceinline__ uint32_t smem_u32(const void* p) {
    uint32_t a;
    asm("{ .reg .u64 t; cvta.to.shared.u64 t, %1; cvt.u32.u64 %0, t; }" : "=r"(a) : "l"(p));
    return a;
}
#define CP_ASYNC(dst, src, sz) \
    asm volatile("cp.async.cg.shared.global [%0], [%1], 16, %2;" \
                 :: "r"(dst), "l"(src), "r"(sz) : "memory")
#define CP_COMMIT() asm volatile("cp.async.commit_group;" ::: "memory")
#define CP_WAIT1()  asm volatile("cp.async.wait_group 1;" ::: "memory")

// ---------------------------------------------------------------------------
// Pre-conversion kernels (fp32 -> tf32 bits)
// ---------------------------------------------------------------------------
__global__ __launch_bounds__(256) void cvt4(const float* __restrict__ x,
                                            uint32_t* __restrict__ y, int n4)
{
    int i = blockIdx.x * 256 + threadIdx.x;
    if (i < n4) {
        float4 v = ((const float4*)x)[i];
        uint4 u;
        u.x = f2tf32(v.x); u.y = f2tf32(v.y);
        u.z = f2tf32(v.z); u.w = f2tf32(v.w);
        ((uint4*)y)[i] = u;
    }
}
__global__ __launch_bounds__(256) void cvt_w(
    const float* __restrict__ Wq, const float* __restrict__ Wk,
    const float* __restrict__ Wv, const float* __restrict__ Wo,
    uint32_t* __restrict__ y)
{
    int z = blockIdx.z;
    const float* src = z < 3 ? Wq + (size_t)z * HH * HH
                     : z < 6 ? Wk + (size_t)(z - 3) * HH * HH
                     : z < 9 ? Wv + (size_t)(z - 6) * HH * HH
                             : Wo;
    uint32_t* dst = y + (size_t)z * HH * HH;
    int i = blockIdx.x * 256 + threadIdx.x;
    float4 v = ((const float4*)src)[i];
    uint4 u;
    u.x = f2tf32(v.x); u.y = f2tf32(v.y);
    u.z = f2tf32(v.z); u.w = f2tf32(v.w);
    ((uint4*)dst)[i] = u;
}

// ---------------------------------------------------------------------------
// cp.async 3-stage BK=32 tf32 mma GEMM with conv halo.
// BM=128, BN=256, 256 threads = 8 warps (2m x 4n), warp tile 64x64.
// Per ks-step per warp: 32 LDS per 32 HMMA (was 24 per 16) — feed-ratio test.
// A smem [m][k] stride 36 (conflict-free). B smem [k][n] stride 256 with
// XOR swizzle n ^ ((k&3)<<3) (conflict-free, same mod-32 math as stride 128).
// Per-element k-accumulation order identical to rounds 4-8: bit-identical.
// ---------------------------------------------------------------------------
#define A_STRIDE 36
#define A_WORDS (128 * A_STRIDE)        // 4608
#define B_WORDS (32 * 256)              // 8192
#define STG_WORDS (A_WORDS + B_WORDS)   // 12800
#define STG_BYTES (STG_WORDS * 4)       // 51200
#define GEMM_DSMEM (3 * STG_BYTES)      // 153600

template <int TAPS, bool HEADS_OUT>
__device__ __forceinline__ void gemm_ca_core(
    const uint32_t* __restrict__ Xc, const uint32_t* __restrict__ Wc,
    const float* __restrict__ bias, void* __restrict__ Yv_, float scale,
    int m0, int n0)
{
    extern __shared__ uint32_t sm[];
    const uint32_t smb = smem_u32(sm);

    const int tid = threadIdx.x;
    const int wid = tid >> 5;
    const int lane = tid & 31;
    const int g = lane >> 2;
    const int tg = lane & 3;
    const int wm = wid >> 2;
    const int wn = wid & 3;
    const int batch = m0 >> 11;
    const int tb = m0 & (SS - 1);
    const int CENTER = (TAPS - 1) / 2;
    const int NIT = TAPS * 32;

    // staging coords: A 4 float4/thread, B 8 float4/thread
    int am[4], ak4[4];
#pragma unroll
    for (int p = 0; p < 4; ++p) {
        int f = tid + p * 256;
        am[p] = f >> 3;
        ak4[p] = (f & 7) << 2;
    }
    int bk[8], bn4[8];
#pragma unroll
    for (int p = 0; p < 8; ++p) {
        int f = tid + p * 256;
        bk[p] = f >> 6;                 // 0..31
        bn4[p] = (f & 63) << 2;         // 0..252
    }

    auto issue = [&](int it) {
        const int tap = it >> 5;
        const int c0 = (it & 31) << 5;
        const uint32_t sb = smb + (uint32_t)(it % 3) * STG_BYTES;
        const uint32_t* wt = Wc + (size_t)tap * HH * HH;
#pragma unroll
        for (int p = 0; p < 4; ++p) {
            int srow = tb + am[p] + tap - CENTER;
            uint32_t sz = 16;
            int sr = srow;
            if (TAPS > 1) {
                sz = (srow >= 0 && srow < SS) ? 16u : 0u;
                sr = srow < 0 ? 0 : (srow >= SS ? SS - 1 : srow);
            }
            const uint32_t* srcA = Xc + ((size_t)batch * SS + sr) * HH + c0 + ak4[p];
            CP_ASYNC(sb + (uint32_t)(am[p] * A_STRIDE + ak4[p]) * 4, srcA, sz);
        }
#pragma unroll
        for (int p = 0; p < 8; ++p) {
            const uint32_t* srcB = wt + (size_t)(c0 + bk[p]) * HH + n0 + bn4[p];
            uint32_t swz = (uint32_t)(bn4[p] ^ ((bk[p] & 3) << 3));
            CP_ASYNC(sb + (A_WORDS + (uint32_t)bk[p] * 256 + swz) * 4, srcB, 16u);
        }
    };

    float acc[4][8][4];
#pragma unroll
    for (int i = 0; i < 4; ++i)
#pragma unroll
        for (int j = 0; j < 8; ++j)
#pragma unroll
            for (int r = 0; r < 4; ++r) acc[i][j][r] = 0.f;

    issue(0); CP_COMMIT();
    issue(1); CP_COMMIT();

    for (int it = 0; it < NIT; ++it) {
        CP_WAIT1();
        __syncthreads();
        if (it + 2 < NIT) issue(it + 2);
        CP_COMMIT();

        const uint32_t* sA = sm + (it % 3) * STG_WORDS;
        const uint32_t* sB = sA + A_WORDS;
#pragma unroll
        for (int ks = 0; ks < 4; ++ks) {
            const int k1 = ks * 8 + tg;
            const int k2 = k1 + 4;
            uint32_t a[4][4], b[8][2];
#pragma unroll
            for (int mt = 0; mt < 4; ++mt) {
                int mr = wm * 64 + mt * 16 + g;
                a[mt][0] = sA[mr * A_STRIDE + k1];
                a[mt][1] = sA[(mr + 8) * A_STRIDE + k1];
                a[mt][2] = sA[mr * A_STRIDE + k2];
                a[mt][3] = sA[(mr + 8) * A_STRIDE + k2];
            }
#pragma unroll
            for (int nt = 0; nt < 8; ++nt) {
                int ncx = (wn * 64 + nt * 8 + g) ^ (tg << 3);
                b[nt][0] = sB[k1 * 256 + ncx];
                b[nt][1] = sB[k2 * 256 + ncx];
            }
#pragma unroll
            for (int mt = 0; mt < 4; ++mt)
#pragma unroll
                for (int nt = 0; nt < 8; ++nt)
                    mma_tf32(acc[mt][nt], a[mt], b[nt]);
        }
    }

    // epilogue
#pragma unroll
    for (int mt = 0; mt < 4; ++mt)
#pragma unroll
        for (int half = 0; half < 2; ++half) {
            int m = m0 + wm * 64 + mt * 16 + g + half * 8;
            int bidx = m >> 11;
            int t = m & (SS - 1);
#pragma unroll
            for (int nt = 0; nt < 8; ++nt) {
                int n = n0 + wn * 64 + nt * 8 + tg * 2;
                float ox = (acc[mt][nt][half * 2 + 0] + bias[n + 0]) * scale;
                float oy = (acc[mt][nt][half * 2 + 1] + bias[n + 1]) * scale;
                if (HEADS_OUT) {
                    int h = n >> 6, d = n & 63;
                    uint2 u;
                    u.x = f2tf32(ox);
                    u.y = f2tf32(oy);
                    *(uint2*)((uint32_t*)Yv_ +
                              (((size_t)bidx * NH + h) * SS + t) * DD + d) = u;
                } else {
                    float2 o = make_float2(ox, oy);
                    *(float2*)((float*)Yv_ + (size_t)m * HH + n) = o;
                }
            }
        }
}

__global__ __launch_bounds__(256, 1) void conv3_ca(
    const uint32_t* __restrict__ Xq, const uint32_t* __restrict__ Xs,
    const uint32_t* __restrict__ Wc,
    const float* __restrict__ bq, const float* __restrict__ bk,
    const float* __restrict__ bv,
    uint32_t* __restrict__ Yq, uint32_t* __restrict__ Yk,
    uint32_t* __restrict__ Yv)
{
    const int z = blockIdx.z;
    gemm_ca_core<3, true>(z ? Xs : Xq, Wc + (size_t)z * 3 * HH * HH,
                          z == 0 ? bq : (z == 1 ? bk : bv),
                          z == 0 ? Yq : (z == 1 ? Yk : Yv),
                          z == 0 ? 0.125f : 1.0f,
                          blockIdx.y * 128, blockIdx.x * 256);
}

__global__ __launch_bounds__(256, 1) void outproj_ca(
    const uint32_t* __restrict__ Xc, const uint32_t* __restrict__ Wc,
    const float* __restrict__ bias, float* __restrict__ Y)
{
    gemm_ca_core<1, false>(Xc, Wc + (size_t)9 * HH * HH, bias, Y, 1.0f,
                           blockIdx.y * 128, blockIdx.x * 256);
}

// ---------------------------------------------------------------------------
// Tensor-core flash attention — unchanged (proven). tf32 bits in/out.
// ---------------------------------------------------------------------------
__global__ __launch_bounds__(256) void attn_tc(const float* __restrict__ mask,
                                               uint32_t* __restrict__ Aout)
{
    __shared__ uint32_t Kn[64][76];
    __shared__ uint32_t Vs[64][72];
    __shared__ float msk[SS];

    const int q0 = blockIdx.x * 128;
    const int h = blockIdx.y;
    const int b = blockIdx.z;
    const int tid = threadIdx.x;
    const int wid = tid >> 5;
    const int lane = tid & 31;
    const int g = lane >> 2;
    const int tg = lane & 3;
    const size_t base = ((size_t)b * NH + h) * SS * DD;
    const int qr = q0 + wid * 16;

    for (int i = tid; i < SS; i += 256)
        msk[i] = mask[(size_t)b * SS + i] * (-1e9f);

    uint32_t qa[8][4];
    {
        const uint32_t* Qp = g_Q + base + (size_t)(qr + g) * DD + tg;
#pragma unroll
        for (int ks = 0; ks < 8; ++ks) {
            qa[ks][0] = Qp[ks * 8];
            qa[ks][1] = Qp[ks * 8 + 8 * DD];
            qa[ks][2] = Qp[ks * 8 + 4];
            qa[ks][3] = Qp[ks * 8 + 4 + 8 * DD];
        }
    }

    float oacc[8][4];
#pragma unroll
    for (int nt = 0; nt < 8; ++nt)
#pragma unroll
        for (int r = 0; r < 4; ++r) oacc[nt][r] = 0.f;
    float m0 = -1e30f, m8 = -1e30f, l0 = 0.f, l8 = 0.f;

    for (int k0 = 0; k0 < SS; k0 += 64) {
        __syncthreads();
#pragma unroll
        for (int p = 0; p < 4; ++p) {
            int f = tid + p * 256;
            int r = f >> 4;
            int c4 = (f & 15) << 2;
            uint4 kv = *(const uint4*)(g_K + base + (size_t)(k0 + r) * DD + c4);
            uint4 vv = *(const uint4*)(g_V + base + (size_t)(k0 + r) * DD + c4);
            *(uint4*)&Kn[r][c4] = kv;
            *(uint4*)&Vs[r][c4] = vv;
        }
        __syncthreads();

        float sacc[8][4];
#pragma unroll
        for (int nt = 0; nt < 8; ++nt)
#pragma unroll
            for (int r = 0; r < 4; ++r) sacc[nt][r] = 0.f;
#pragma unroll
        for (int ks = 0; ks < 8; ++ks)
#pragma unroll
            for (int nt = 0; nt < 8; ++nt) {
                uint32_t bfr[2];
                bfr[0] = Kn[nt * 8 + g][ks * 8 + tg];
                bfr[1] = Kn[nt * 8 + g][ks * 8 + tg + 4];
                mma_tf32(sacc[nt], qa[ks], bfr);
            }

#pragma unroll
        for (int nt = 0; nt < 8; ++nt) {
            float mk0 = msk[k0 + nt * 8 + 2 * tg];
            float mk1 = msk[k0 + nt * 8 + 2 * tg + 1];
            sacc[nt][0] += mk0; sacc[nt][1] += mk1;
            sacc[nt][2] += mk0; sacc[nt][3] += mk1;
        }

        float r0 = -1e30f, r8 = -1e30f;
#pragma unroll
        for (int nt = 0; nt < 8; ++nt) {
            r0 = fmaxf(r0, fmaxf(sacc[nt][0], sacc[nt][1]));
            r8 = fmaxf(r8, fmaxf(sacc[nt][2], sacc[nt][3]));
        }
        r0 = fmaxf(r0, __shfl_xor_sync(0xffffffffu, r0, 1));
        r0 = fmaxf(r0, __shfl_xor_sync(0xffffffffu, r0, 2));
        r8 = fmaxf(r8, __shfl_xor_sync(0xffffffffu, r8, 1));
        r8 = fmaxf(r8, __shfl_xor_sync(0xffffffffu, r8, 2));

        float nm0 = fmaxf(m0, r0), nm8 = fmaxf(m8, r8);
        float cr0 = __expf(m0 - nm0), cr8 = __expf(m8 - nm8);

        float s0 = 0.f, s8 = 0.f;
#pragma unroll
        for (int nt = 0; nt < 8; ++nt) {
            sacc[nt][0] = __expf(sacc[nt][0] - nm0);
            sacc[nt][1] = __expf(sacc[nt][1] - nm0);
            sacc[nt][2] = __expf(sacc[nt][2] - nm8);
            sacc[nt][3] = __expf(sacc[nt][3] - nm8);
            s0 += sacc[nt][0] + sacc[nt][1];
            s8 += sacc[nt][2] + sacc[nt][3];
        }
        s0 += __shfl_xor_sync(0xffffffffu, s0, 1);
        s0 += __shfl_xor_sync(0xffffffffu, s0, 2);
        s8 += __shfl_xor_sync(0xffffffffu, s8, 1);
        s8 += __shfl_xor_sync(0xffffffffu, s8, 2);

        l0 = l0 * cr0 + s0;
        l8 = l8 * cr8 + s8;
        m0 = nm0; m8 = nm8;

#pragma unroll
        for (int nt = 0; nt < 8; ++nt) {
            oacc[nt][0] *= cr0; oacc[nt][1] *= cr0;
            oacc[nt][2] *= cr8; oacc[nt][3] *= cr8;
        }

        const int src0 = (g << 2) + (tg >> 1);
        const int src2 = src0 + 2;
        const bool odd = tg & 1;
#pragma unroll
        for (int ks = 0; ks < 8; ++ks) {
            float e00 = __shfl_sync(0xffffffffu, sacc[ks][0], src0);
            float e01 = __shfl_sync(0xffffffffu, sacc[ks][1], src0);
            float e10 = __shfl_sync(0xffffffffu, sacc[ks][2], src0);
            float e11 = __shfl_sync(0xffffffffu, sacc[ks][3], src0);
            float e20 = __shfl_sync(0xffffffffu, sacc[ks][0], src2);
            float e21 = __shfl_sync(0xffffffffu, sacc[ks][1], src2);
            float e30 = __shfl_sync(0xffffffffu, sacc[ks][2], src2);
            float e31 = __shfl_sync(0xffffffffu, sacc[ks][3], src2);
            uint32_t pa[4];
            pa[0] = f2tf32(odd ? e01 : e00);
            pa[1] = f2tf32(odd ? e11 : e10);
            pa[2] = f2tf32(odd ? e21 : e20);
            pa[3] = f2tf32(odd ? e31 : e30);
#pragma unroll
            for (int nt = 0; nt < 8; ++nt) {
                uint32_t bfr[2];
                bfr[0] = Vs[ks * 8 + tg][nt * 8 + g];
                bfr[1] = Vs[ks * 8 + tg + 4][nt * 8 + g];
                mma_tf32(oacc[nt], pa, bfr);
            }
        }
    }

    const float inv0 = 1.f / l0, inv8 = 1.f / l8;
#pragma unroll
    for (int nt = 0; nt < 8; ++nt) {
        uint2 o0, o8;
        o0.x = f2tf32(oacc[nt][0] * inv0); o0.y = f2tf32(oacc[nt][1] * inv0);
        o8.x = f2tf32(oacc[nt][2] * inv8); o8.y = f2tf32(oacc[nt][3] * inv8);
        size_t col = (size_t)h * DD + nt * 8 + 2 * tg;
        *(uint2*)(Aout + ((size_t)b * SS + qr + g) * HH + col) = o0;
        *(uint2*)(Aout + ((size_t)b * SS + qr + g + 8) * HH + col) = o8;
    }
}

// ---------------------------------------------------------------------------
extern "C" void kernel_launch(void* const* d_in, const int* in_sizes, int n_in,
                              void* d_out, int out_size)
{
    const float* qin  = (const float*)d_in[0];
    const float* src  = (const float*)d_in[1];
    const float* mask = (const float*)d_in[2];
    const float* Wq   = (const float*)d_in[3];
    const float* bq   = (const float*)d_in[4];
    const float* Wk   = (const float*)d_in[5];
    const float* bk   = (const float*)d_in[6];
    const float* Wv   = (const float*)d_in[7];
    const float* bv   = (const float*)d_in[8];
    const float* Wo   = (const float*)d_in[9];
    const float* bo   = (const float*)d_in[10];
    float* out = (float*)d_out;

    uint32_t *gQ, *gK, *gV, *gAc, *gXq, *gXs, *gW;
    cudaGetSymbolAddress((void**)&gQ, g_Q);
    cudaGetSymbolAddress((void**)&gK, g_K);
    cudaGetSymbolAddress((void**)&gV, g_V);
    cudaGetSymbolAddress((void**)&gAc, g_Ac);
    cudaGetSymbolAddress((void**)&gXq, g_Xqc);
    cudaGetSymbolAddress((void**)&gXs, g_Xsc);
    cudaGetSymbolAddress((void**)&gW, g_Wc);

    cudaFuncSetAttribute(conv3_ca, cudaFuncAttributeMaxDynamicSharedMemorySize,
                         GEMM_DSMEM);
    cudaFuncSetAttribute(outproj_ca, cudaFuncAttributeMaxDynamicSharedMemorySize,
                         GEMM_DSMEM);

    const int N4 = BB * SS * HH / 4;
    cvt4<<<(N4 + 255) / 256, 256>>>(qin, gXq, N4);
    cvt4<<<(N4 + 255) / 256, 256>>>(src, gXs, N4);
    dim3 gridW(HH * HH / 4 / 256, 1, 10);
    cvt_w<<<gridW, 256>>>(Wq, Wk, Wv, Wo, gW);

    dim3 gridC(HH / 256, (BB * SS) / 128, 3);     // (4, 32, 3)
    conv3_ca<<<gridC, 256, GEMM_DSMEM>>>(gXq, gXs, gW, bq, bk, bv, gQ, gK, gV);

    dim3 gridAttn(SS / 128, NH, BB);              // (16, 16, 2)
    attn_tc<<<gridAttn, 256>>>(mask, gAc);

    dim3 gridO(HH / 256, (BB * SS) / 128);        // (4, 32)
    outproj_ca<<<gridO, 256, GEMM_DSMEM>>>(gAc, gW, bo, out);
}

// round 10
// speedup vs baseline: 1.1448x; 1.1097x over previous
#include <cuda_runtime.h>
#include <math.h>
#include <stdint.h>

#define BB 2
#define SS 2048
#define HH 1024
#define NH 16
#define DD 64

// Scratch: Q/K/V and attention output stored as tf32 BITS (uint32)
__device__ uint32_t g_Q[(size_t)BB * NH * SS * DD];
__device__ uint32_t g_K[(size_t)BB * NH * SS * DD];
__device__ uint32_t g_V[(size_t)BB * NH * SS * DD];
__device__ uint32_t g_Ac[(size_t)BB * SS * HH];
__device__ uint32_t g_Xqc[(size_t)BB * SS * HH];
__device__ uint32_t g_Xsc[(size_t)BB * SS * HH];
__device__ uint32_t g_Wc[(size_t)10 * HH * HH];  // Wq(3) Wk(3) Wv(3) Wo(1), [k][n]

// ---------------------------------------------------------------------------
__device__ __forceinline__ uint32_t f2tf32(float x) {
    uint32_t r;
    asm("cvt.rna.tf32.f32 %0, %1;" : "=r"(r) : "f"(x));
    return r;
}
__device__ __forceinline__ void mma_tf32(float* d, const uint32_t* a, const uint32_t* b) {
    asm volatile(
        "mma.sync.aligned.m16n8k8.row.col.f32.tf32.tf32.f32 "
        "{%0,%1,%2,%3}, {%4,%5,%6,%7}, {%8,%9}, {%0,%1,%2,%3};"
        : "+f"(d[0]), "+f"(d[1]), "+f"(d[2]), "+f"(d[3])
        : "r"(a[0]), "r"(a[1]), "r"(a[2]), "r"(a[3]), "r"(b[0]), "r"(b[1]));
}
__device__ __forceinline__ uint32_t smem_u32(const void* p) {
    uint32_t a;
    asm("{ .reg .u64 t; cvta.to.shared.u64 t, %1; cvt.u32.u64 %0, t; }" : "=r"(a) : "l"(p));
    return a;
}
#define CP_ASYNC(dst, src, sz) \
    asm volatile("cp.async.cg.shared.global [%0], [%1], 16, %2;" \
                 :: "r"(dst), "l"(src), "r"(sz) : "memory")
#define CP_COMMIT() asm volatile("cp.async.commit_group;" ::: "memory")
#define CP_WAIT1()  asm volatile("cp.async.wait_group 1;" ::: "memory")
#define CP_WAIT2()  asm volatile("cp.async.wait_group 2;" ::: "memory")

// ---------------------------------------------------------------------------
// Pre-conversion kernels (fp32 -> tf32 bits)
// ---------------------------------------------------------------------------
__global__ __launch_bounds__(256) void cvt4(const float* __restrict__ x,
                                            uint32_t* __restrict__ y, int n4)
{
    int i = blockIdx.x * 256 + threadIdx.x;
    if (i < n4) {
        float4 v = ((const float4*)x)[i];
        uint4 u;
        u.x = f2tf32(v.x); u.y = f2tf32(v.y);
        u.z = f2tf32(v.z); u.w = f2tf32(v.w);
        ((uint4*)y)[i] = u;
    }
}
__global__ __launch_bounds__(256) void cvt_w(
    const float* __restrict__ Wq, const float* __restrict__ Wk,
    const float* __restrict__ Wv, const float* __restrict__ Wo,
    uint32_t* __restrict__ y)
{
    int z = blockIdx.z;
    const float* src = z < 3 ? Wq + (size_t)z * HH * HH
                     : z < 6 ? Wk + (size_t)(z - 3) * HH * HH
                     : z < 9 ? Wv + (size_t)(z - 6) * HH * HH
                             : Wo;
    uint32_t* dst = y + (size_t)z * HH * HH;
    int i = blockIdx.x * 256 + threadIdx.x;
    float4 v = ((const float4*)src)[i];
    uint4 u;
    u.x = f2tf32(v.x); u.y = f2tf32(v.y);
    u.z = f2tf32(v.z); u.w = f2tf32(v.w);
    ((uint4*)dst)[i] = u;
}

// ---------------------------------------------------------------------------
// cp.async 3-stage BK=32 tf32 mma GEMM (unchanged from round 9 — at the
// legacy tf32 HMMA ceiling). BM=128, BN=256, warp tile 64x64.
// ---------------------------------------------------------------------------
#define A_STRIDE 36
#define A_WORDS (128 * A_STRIDE)
#define B_WORDS (32 * 256)
#define STG_WORDS (A_WORDS + B_WORDS)
#define STG_BYTES (STG_WORDS * 4)
#define GEMM_DSMEM (3 * STG_BYTES)

template <int TAPS, bool HEADS_OUT>
__device__ __forceinline__ void gemm_ca_core(
    const uint32_t* __restrict__ Xc, const uint32_t* __restrict__ Wc,
    const float* __restrict__ bias, void* __restrict__ Yv_, float scale,
    int m0, int n0)
{
    extern __shared__ uint32_t sm[];
    const uint32_t smb = smem_u32(sm);

    const int tid = threadIdx.x;
    const int wid = tid >> 5;
    const int lane = tid & 31;
    const int g = lane >> 2;
    const int tg = lane & 3;
    const int wm = wid >> 2;
    const int wn = wid & 3;
    const int batch = m0 >> 11;
    const int tb = m0 & (SS - 1);
    const int CENTER = (TAPS - 1) / 2;
    const int NIT = TAPS * 32;

    int am[4], ak4[4];
#pragma unroll
    for (int p = 0; p < 4; ++p) {
        int f = tid + p * 256;
        am[p] = f >> 3;
        ak4[p] = (f & 7) << 2;
    }
    int bk[8], bn4[8];
#pragma unroll
    for (int p = 0; p < 8; ++p) {
        int f = tid + p * 256;
        bk[p] = f >> 6;
        bn4[p] = (f & 63) << 2;
    }

    auto issue = [&](int it) {
        const int tap = it >> 5;
        const int c0 = (it & 31) << 5;
        const uint32_t sb = smb + (uint32_t)(it % 3) * STG_BYTES;
        const uint32_t* wt = Wc + (size_t)tap * HH * HH;
#pragma unroll
        for (int p = 0; p < 4; ++p) {
            int srow = tb + am[p] + tap - CENTER;
            uint32_t sz = 16;
            int sr = srow;
            if (TAPS > 1) {
                sz = (srow >= 0 && srow < SS) ? 16u : 0u;
                sr = srow < 0 ? 0 : (srow >= SS ? SS - 1 : srow);
            }
            const uint32_t* srcA = Xc + ((size_t)batch * SS + sr) * HH + c0 + ak4[p];
            CP_ASYNC(sb + (uint32_t)(am[p] * A_STRIDE + ak4[p]) * 4, srcA, sz);
        }
#pragma unroll
        for (int p = 0; p < 8; ++p) {
            const uint32_t* srcB = wt + (size_t)(c0 + bk[p]) * HH + n0 + bn4[p];
            uint32_t swz = (uint32_t)(bn4[p] ^ ((bk[p] & 3) << 3));
            CP_ASYNC(sb + (A_WORDS + (uint32_t)bk[p] * 256 + swz) * 4, srcB, 16u);
        }
    };

    float acc[4][8][4];
#pragma unroll
    for (int i = 0; i < 4; ++i)
#pragma unroll
        for (int j = 0; j < 8; ++j)
#pragma unroll
            for (int r = 0; r < 4; ++r) acc[i][j][r] = 0.f;

    issue(0); CP_COMMIT();
    issue(1); CP_COMMIT();

    for (int it = 0; it < NIT; ++it) {
        CP_WAIT1();
        __syncthreads();
        if (it + 2 < NIT) issue(it + 2);
        CP_COMMIT();

        const uint32_t* sA = sm + (it % 3) * STG_WORDS;
        const uint32_t* sB = sA + A_WORDS;
#pragma unroll
        for (int ks = 0; ks < 4; ++ks) {
            const int k1 = ks * 8 + tg;
            const int k2 = k1 + 4;
            uint32_t a[4][4], b[8][2];
#pragma unroll
            for (int mt = 0; mt < 4; ++mt) {
                int mr = wm * 64 + mt * 16 + g;
                a[mt][0] = sA[mr * A_STRIDE + k1];
                a[mt][1] = sA[(mr + 8) * A_STRIDE + k1];
                a[mt][2] = sA[mr * A_STRIDE + k2];
                a[mt][3] = sA[(mr + 8) * A_STRIDE + k2];
            }
#pragma unroll
            for (int nt = 0; nt < 8; ++nt) {
                int ncx = (wn * 64 + nt * 8 + g) ^ (tg << 3);
                b[nt][0] = sB[k1 * 256 + ncx];
                b[nt][1] = sB[k2 * 256 + ncx];
            }
#pragma unroll
            for (int mt = 0; mt < 4; ++mt)
#pragma unroll
                for (int nt = 0; nt < 8; ++nt)
                    mma_tf32(acc[mt][nt], a[mt], b[nt]);
        }
    }

#pragma unroll
    for (int mt = 0; mt < 4; ++mt)
#pragma unroll
        for (int half = 0; half < 2; ++half) {
            int m = m0 + wm * 64 + mt * 16 + g + half * 8;
            int bidx = m >> 11;
            int t = m & (SS - 1);
#pragma unroll
            for (int nt = 0; nt < 8; ++nt) {
                int n = n0 + wn * 64 + nt * 8 + tg * 2;
                float ox = (acc[mt][nt][half * 2 + 0] + bias[n + 0]) * scale;
                float oy = (acc[mt][nt][half * 2 + 1] + bias[n + 1]) * scale;
                if (HEADS_OUT) {
                    int h = n >> 6, d = n & 63;
                    uint2 u;
                    u.x = f2tf32(ox);
                    u.y = f2tf32(oy);
                    *(uint2*)((uint32_t*)Yv_ +
                              (((size_t)bidx * NH + h) * SS + t) * DD + d) = u;
                } else {
                    float2 o = make_float2(ox, oy);
                    *(float2*)((float*)Yv_ + (size_t)m * HH + n) = o;
                }
            }
        }
}

__global__ __launch_bounds__(256, 1) void conv3_ca(
    const uint32_t* __restrict__ Xq, const uint32_t* __restrict__ Xs,
    const uint32_t* __restrict__ Wc,
    const float* __restrict__ bq, const float* __restrict__ bk,
    const float* __restrict__ bv,
    uint32_t* __restrict__ Yq, uint32_t* __restrict__ Yk,
    uint32_t* __restrict__ Yv)
{
    const int z = blockIdx.z;
    gemm_ca_core<3, true>(z ? Xs : Xq, Wc + (size_t)z * 3 * HH * HH,
                          z == 0 ? bq : (z == 1 ? bk : bv),
                          z == 0 ? Yq : (z == 1 ? Yk : Yv),
                          z == 0 ? 0.125f : 1.0f,
                          blockIdx.y * 128, blockIdx.x * 256);
}

__global__ __launch_bounds__(256, 1) void outproj_ca(
    const uint32_t* __restrict__ Xc, const uint32_t* __restrict__ Wc,
    const float* __restrict__ bias, float* __restrict__ Y)
{
    gemm_ca_core<1, false>(Xc, Wc + (size_t)9 * HH * HH, bias, Y, 1.0f,
                           blockIdx.y * 128, blockIdx.x * 256);
}

// ---------------------------------------------------------------------------
// Attention v3: permuted-key staging (zero-shfl P transpose) +
// cp.async 4-buffer K/V pipeline, ONE sync per key tile.
// K staged with per-8-group key permutation [0,4,1,5,2,6,3,7] so that the
// S-accumulator C-fragment IS the PV A-fragment (up to register reorder).
// V unpermuted (A k-slot k meets V row k directly).
// ---------------------------------------------------------------------------
#define KN_W (64 * 76)              // 4864 words per K buffer (stride 76)
#define VS_W (64 * 72)              // 4608 words per V buffer (stride 72)
#define BUF_W (KN_W + VS_W)         // 9472
#define MSK_OFF (4 * BUF_W)         // 37888
#define ATTN_DSMEM ((MSK_OFF + SS) * 4)   // 159744 bytes

__global__ __launch_bounds__(256, 1) void attn_tc(const float* __restrict__ mask,
                                                  uint32_t* __restrict__ Aout)
{
    extern __shared__ uint32_t sm[];
    const uint32_t smb = smem_u32(sm);
    float* msk = (float*)(sm + MSK_OFF);

    const int q0 = blockIdx.x * 128;
    const int h = blockIdx.y;
    const int b = blockIdx.z;
    const int tid = threadIdx.x;
    const int wid = tid >> 5;
    const int lane = tid & 31;
    const int g = lane >> 2;
    const int tg = lane & 3;
    const size_t base = ((size_t)b * NH + h) * SS * DD;
    const int qr = q0 + wid * 16;

    for (int i = tid; i < SS; i += 256)
        msk[i] = mask[(size_t)b * SS + i] * (-1e9f);

    uint32_t qa[8][4];
    {
        const uint32_t* Qp = g_Q + base + (size_t)(qr + g) * DD + tg;
#pragma unroll
        for (int ks = 0; ks < 8; ++ks) {
            qa[ks][0] = Qp[ks * 8];
            qa[ks][1] = Qp[ks * 8 + 8 * DD];
            qa[ks][2] = Qp[ks * 8 + 4];
            qa[ks][3] = Qp[ks * 8 + 4 + 8 * DD];
        }
    }

    // per-thread staging coords (4 rows of 64, one float4 column each)
    int sr[4], sc4[4], slk[4];
#pragma unroll
    for (int p = 0; p < 4; ++p) {
        int f = tid + p * 256;
        sr[p] = f >> 4;
        sc4[p] = (f & 15) << 2;
        int r = sr[p];
        slk[p] = (r & 56) | ((r & 7) >> 1) | ((r & 1) << 2);  // key permutation
    }

    auto stage = [&](int t) {
        const int buf = t & 3;
        const int k0 = t << 6;
#pragma unroll
        for (int p = 0; p < 4; ++p) {
            CP_ASYNC(smb + (uint32_t)(buf * BUF_W + sr[p] * 76 + sc4[p]) * 4,
                     g_K + base + (size_t)(k0 + slk[p]) * DD + sc4[p], 16u);
            CP_ASYNC(smb + (uint32_t)(buf * BUF_W + KN_W + sr[p] * 72 + sc4[p]) * 4,
                     g_V + base + (size_t)(k0 + sr[p]) * DD + sc4[p], 16u);
        }
    };

    float oacc[8][4];
#pragma unroll
    for (int nt = 0; nt < 8; ++nt)
#pragma unroll
        for (int r = 0; r < 4; ++r) oacc[nt][r] = 0.f;
    float m0 = -1e30f, m8 = -1e30f, l0 = 0.f, l8 = 0.f;

    stage(0); CP_COMMIT();
    stage(1); CP_COMMIT();

    for (int t = 0; t < 32; ++t) {
        if (t + 2 < 32) stage(t + 2);
        CP_COMMIT();
        CP_WAIT2();
        __syncthreads();

        const uint32_t* Kb = sm + (t & 3) * BUF_W;
        const uint32_t* Vb = Kb + KN_W;
        const int k0 = t << 6;

        float sacc[8][4];
#pragma unroll
        for (int nt = 0; nt < 8; ++nt)
#pragma unroll
            for (int r = 0; r < 4; ++r) sacc[nt][r] = 0.f;
#pragma unroll
        for (int ks = 0; ks < 8; ++ks)
#pragma unroll
            for (int nt = 0; nt < 8; ++nt) {
                uint32_t bfr[2];
                bfr[0] = Kb[(nt * 8 + g) * 76 + ks * 8 + tg];
                bfr[1] = Kb[(nt * 8 + g) * 76 + ks * 8 + tg + 4];
                mma_tf32(sacc[nt], qa[ks], bfr);
            }

        // additive mask with permuted column indexing:
        // phys col 2tg -> logical key tg; phys col 2tg+1 -> key tg+4
#pragma unroll
        for (int nt = 0; nt < 8; ++nt) {
            float mk0 = msk[k0 + nt * 8 + tg];
            float mk1 = msk[k0 + nt * 8 + tg + 4];
            sacc[nt][0] += mk0; sacc[nt][1] += mk1;
            sacc[nt][2] += mk0; sacc[nt][3] += mk1;
        }

        float r0 = -1e30f, r8 = -1e30f;
#pragma unroll
        for (int nt = 0; nt < 8; ++nt) {
            r0 = fmaxf(r0, fmaxf(sacc[nt][0], sacc[nt][1]));
            r8 = fmaxf(r8, fmaxf(sacc[nt][2], sacc[nt][3]));
        }
        r0 = fmaxf(r0, __shfl_xor_sync(0xffffffffu, r0, 1));
        r0 = fmaxf(r0, __shfl_xor_sync(0xffffffffu, r0, 2));
        r8 = fmaxf(r8, __shfl_xor_sync(0xffffffffu, r8, 1));
        r8 = fmaxf(r8, __shfl_xor_sync(0xffffffffu, r8, 2));

        float nm0 = fmaxf(m0, r0), nm8 = fmaxf(m8, r8);
        float cr0 = __expf(m0 - nm0), cr8 = __expf(m8 - nm8);

        float s0 = 0.f, s8 = 0.f;
#pragma unroll
        for (int nt = 0; nt < 8; ++nt) {
            sacc[nt][0] = __expf(sacc[nt][0] - nm0);
            sacc[nt][1] = __expf(sacc[nt][1] - nm0);
            sacc[nt][2] = __expf(sacc[nt][2] - nm8);
            sacc[nt][3] = __expf(sacc[nt][3] - nm8);
            s0 += sacc[nt][0] + sacc[nt][1];
            s8 += sacc[nt][2] + sacc[nt][3];
        }
        s0 += __shfl_xor_sync(0xffffffffu, s0, 1);
        s0 += __shfl_xor_sync(0xffffffffu, s0, 2);
        s8 += __shfl_xor_sync(0xffffffffu, s8, 1);
        s8 += __shfl_xor_sync(0xffffffffu, s8, 2);

        l0 = l0 * cr0 + s0;
        l8 = l8 * cr8 + s8;
        m0 = nm0; m8 = nm8;

#pragma unroll
        for (int nt = 0; nt < 8; ++nt) {
            oacc[nt][0] *= cr0; oacc[nt][1] *= cr0;
            oacc[nt][2] *= cr8; oacc[nt][3] *= cr8;
        }

        // O += P V : C-fragment == A-fragment after register reorder (no shfl)
#pragma unroll
        for (int ks = 0; ks < 8; ++ks) {
            uint32_t pa[4];
            pa[0] = f2tf32(sacc[ks][0]);   // row g,   k=tg
            pa[1] = f2tf32(sacc[ks][2]);   // row g+8, k=tg
            pa[2] = f2tf32(sacc[ks][1]);   // row g,   k=tg+4
            pa[3] = f2tf32(sacc[ks][3]);   // row g+8, k=tg+4
#pragma unroll
            for (int nt = 0; nt < 8; ++nt) {
                uint32_t bfr[2];
                bfr[0] = Vb[(ks * 8 + tg) * 72 + nt * 8 + g];
                bfr[1] = Vb[(ks * 8 + tg + 4) * 72 + nt * 8 + g];
                mma_tf32(oacc[nt], pa, bfr);
            }
        }
    }

    const float inv0 = 1.f / l0, inv8 = 1.f / l8;
#pragma unroll
    for (int nt = 0; nt < 8; ++nt) {
        uint2 o0, o8;
        o0.x = f2tf32(oacc[nt][0] * inv0); o0.y = f2tf32(oacc[nt][1] * inv0);
        o8.x = f2tf32(oacc[nt][2] * inv8); o8.y = f2tf32(oacc[nt][3] * inv8);
        size_t col = (size_t)h * DD + nt * 8 + 2 * tg;
        *(uint2*)(Aout + ((size_t)b * SS + qr + g) * HH + col) = o0;
        *(uint2*)(Aout + ((size_t)b * SS + qr + g + 8) * HH + col) = o8;
    }
}

// ---------------------------------------------------------------------------
extern "C" void kernel_launch(void* const* d_in, const int* in_sizes, int n_in,
                              void* d_out, int out_size)
{
    const float* qin  = (const float*)d_in[0];
    const float* src  = (const float*)d_in[1];
    const float* mask = (const float*)d_in[2];
    const float* Wq   = (const float*)d_in[3];
    const float* bq   = (const float*)d_in[4];
    const float* Wk   = (const float*)d_in[5];
    const float* bk   = (const float*)d_in[6];
    const float* Wv   = (const float*)d_in[7];
    const float* bv   = (const float*)d_in[8];
    const float* Wo   = (const float*)d_in[9];
    const float* bo   = (const float*)d_in[10];
    float* out = (float*)d_out;

    uint32_t *gQ, *gK, *gV, *gAc, *gXq, *gXs, *gW;
    cudaGetSymbolAddress((void**)&gQ, g_Q);
    cudaGetSymbolAddress((void**)&gK, g_K);
    cudaGetSymbolAddress((void**)&gV, g_V);
    cudaGetSymbolAddress((void**)&gAc, g_Ac);
    cudaGetSymbolAddress((void**)&gXq, g_Xqc);
    cudaGetSymbolAddress((void**)&gXs, g_Xsc);
    cudaGetSymbolAddress((void**)&gW, g_Wc);

    cudaFuncSetAttribute(conv3_ca, cudaFuncAttributeMaxDynamicSharedMemorySize,
                         GEMM_DSMEM);
    cudaFuncSetAttribute(outproj_ca, cudaFuncAttributeMaxDynamicSharedMemorySize,
                         GEMM_DSMEM);
    cudaFuncSetAttribute(attn_tc, cudaFuncAttributeMaxDynamicSharedMemorySize,
                         ATTN_DSMEM);

    const int N4 = BB * SS * HH / 4;
    cvt4<<<(N4 + 255) / 256, 256>>>(qin, gXq, N4);
    cvt4<<<(N4 + 255) / 256, 256>>>(src, gXs, N4);
    dim3 gridW(HH * HH / 4 / 256, 1, 10);
    cvt_w<<<gridW, 256>>>(Wq, Wk, Wv, Wo, gW);

    dim3 gridC(HH / 256, (BB * SS) / 128, 3);     // (4, 32, 3)
    conv3_ca<<<gridC, 256, GEMM_DSMEM>>>(gXq, gXs, gW, bq, bk, bv, gQ, gK, gV);

    dim3 gridAttn(SS / 128, NH, BB);              // (16, 16, 2)
    attn_tc<<<gridAttn, 256, ATTN_DSMEM>>>(mask, gAc);

    dim3 gridO(HH / 256, (BB * SS) / 128);        // (4, 32)
    outproj_ca<<<gridO, 256, GEMM_DSMEM>>>(gAc, gW, bo, out);
}

// round 11
// speedup vs baseline: 1.8502x; 1.6163x over previous
#include <cuda_runtime.h>
#include <cuda_fp16.h>
#include <math.h>
#include <stdint.h>

#define BB 2
#define SS 2048
#define HH 1024
#define NH 16
#define DD 64
#define HW (HH / 2)     // packed words per row

// Scratch, all fp16x2-packed words unless noted
__device__ uint32_t g_Q[(size_t)BB * NH * SS * (DD / 2)];
__device__ uint32_t g_K[(size_t)BB * NH * SS * (DD / 2)];
__device__ uint32_t g_V[(size_t)BB * NH * SS * (DD / 2)];
__device__ uint32_t g_Vt[(size_t)BB * NH * DD * (SS / 2)];  // [bh][d][keypair]
__device__ uint32_t g_Ac[(size_t)BB * SS * HW];
__device__ uint32_t g_Xqc[(size_t)BB * SS * HW];
__device__ uint32_t g_Xsc[(size_t)BB * SS * HW];
__device__ uint32_t g_Wc[(size_t)10 * HW * HH];  // [kp][n] k-pair packed

// ---------------------------------------------------------------------------
__device__ __forceinline__ uint32_t pack_h2(float a, float b) {
    __half2 h = __floats2half2_rn(a, b);
    return *reinterpret_cast<uint32_t*>(&h);
}
__device__ __forceinline__ void mma_f16(float* d, const uint32_t* a, const uint32_t* b) {
    asm volatile(
        "mma.sync.aligned.m16n8k16.row.col.f32.f16.f16.f32 "
        "{%0,%1,%2,%3}, {%4,%5,%6,%7}, {%8,%9}, {%0,%1,%2,%3};"
        : "+f"(d[0]), "+f"(d[1]), "+f"(d[2]), "+f"(d[3])
        : "r"(a[0]), "r"(a[1]), "r"(a[2]), "r"(a[3]), "r"(b[0]), "r"(b[1]));
}
__device__ __forceinline__ uint32_t smem_u32(const void* p) {
    uint32_t a;
    asm("{ .reg .u64 t; cvta.to.shared.u64 t, %1; cvt.u32.u64 %0, t; }" : "=r"(a) : "l"(p));
    return a;
}
#define CP_ASYNC(dst, src, sz) \
    asm volatile("cp.async.cg.shared.global [%0], [%1], 16, %2;" \
                 :: "r"(dst), "l"(src), "r"(sz) : "memory")
#define CP_COMMIT() asm volatile("cp.async.commit_group;" ::: "memory")
#define CP_WAIT1()  asm volatile("cp.async.wait_group 1;" ::: "memory")
#define CP_WAIT2()  asm volatile("cp.async.wait_group 2;" ::: "memory")

// ---------------------------------------------------------------------------
// fp32 -> packed fp16 conversions
// ---------------------------------------------------------------------------
__global__ __launch_bounds__(256) void cvt4(const float* __restrict__ x,
                                            uint32_t* __restrict__ y, int n4)
{
    int i = blockIdx.x * 256 + threadIdx.x;
    if (i < n4) {
        float4 v = ((const float4*)x)[i];
        uint2 u;
        u.x = pack_h2(v.x, v.y);
        u.y = pack_h2(v.z, v.w);
        ((uint2*)y)[i] = u;
    }
}
// Pack weights k-pairwise: out[kp][n] = (W[2kp][n], W[2kp+1][n])
__global__ __launch_bounds__(256) void cvt_w(
    const float* __restrict__ Wq, const float* __restrict__ Wk,
    const float* __restrict__ Wv, const float* __restrict__ Wo,
    uint32_t* __restrict__ y)
{
    int z = blockIdx.z;
    const float* src = z < 3 ? Wq + (size_t)z * HH * HH
                     : z < 6 ? Wk + (size_t)(z - 3) * HH * HH
                     : z < 9 ? Wv + (size_t)(z - 6) * HH * HH
                             : Wo;
    uint32_t* dst = y + (size_t)z * HW * HH;
    int i = blockIdx.x * 256 + threadIdx.x;    // over HW*HH words
    int kp = i >> 10;
    int n = i & 1023;
    dst[i] = pack_h2(src[(size_t)(2 * kp) * HH + n],
                     src[(size_t)(2 * kp + 1) * HH + n]);
}
// V [bh][key][dp] -> Vt [bh][d][keyp]  (key-pair packed along d rows)
__global__ __launch_bounds__(256) void repack_v(
    const uint32_t* __restrict__ V, uint32_t* __restrict__ Vt)
{
    __shared__ __half smh[64][66];
    const int bh = blockIdx.y;
    const int kt = blockIdx.x;
    const uint32_t* src = V + ((size_t)bh * SS + kt * 64) * (DD / 2);
    for (int f = threadIdx.x; f < 64 * 32; f += 256) {
        int key = f >> 5, w = f & 31;
        uint32_t u = src[key * 32 + w];
        __half2 h = *reinterpret_cast<__half2*>(&u);
        smh[key][w * 2] = h.x;
        smh[key][w * 2 + 1] = h.y;
    }
    __syncthreads();
    uint32_t* dst = Vt + (size_t)bh * DD * (SS / 2) + kt * 32;
    for (int f = threadIdx.x; f < 64 * 32; f += 256) {
        int d = f >> 5, kp = f & 31;
        dst[(size_t)d * (SS / 2) + kp] =
            pack_h2(__half2float(smh[2 * kp][d]), __half2float(smh[2 * kp + 1][d]));
    }
}

// ---------------------------------------------------------------------------
// cp.async 3-stage BK=32 fp16 mma GEMM with conv halo.
// BM=128, BN=256, 8 warps (2m x 4n), warp tile 64x64, m16n8k16.
// A smem [m][kp] stride 20 (frag bank 20g+tg: conflict-free).
// B smem [kp][n] stride 256 with swizzle n ^ ((kp&3)<<3) (conflict-free).
// ---------------------------------------------------------------------------
#define A_STRIDE 20
#define A_WORDS (128 * A_STRIDE)        // 2560
#define B_WORDS (16 * 256)              // 4096
#define STG_WORDS (A_WORDS + B_WORDS)   // 6656
#define STG_BYTES (STG_WORDS * 4)       // 26624
#define GEMM_DSMEM (3 * STG_BYTES)      // 79872

template <int TAPS, bool HEADS_OUT>
__device__ __forceinline__ void gemm_ca_core(
    const uint32_t* __restrict__ Xc, const uint32_t* __restrict__ Wc,
    const float* __restrict__ bias, void* __restrict__ Yv_, float scale,
    int m0, int n0)
{
    extern __shared__ uint32_t sm[];
    const uint32_t smb = smem_u32(sm);

    const int tid = threadIdx.x;
    const int wid = tid >> 5;
    const int lane = tid & 31;
    const int g = lane >> 2;
    const int tg = lane & 3;
    const int wm = wid >> 2;
    const int wn = wid & 3;
    const int batch = m0 >> 11;
    const int tb = m0 & (SS - 1);
    const int CENTER = (TAPS - 1) / 2;
    const int NIT = TAPS * 32;

    // A staging: 2048 words/chunk, 2 cp per thread
    int am[2], ac4[2];
#pragma unroll
    for (int p = 0; p < 2; ++p) {
        int f = tid + p * 256;
        am[p] = f >> 2;
        ac4[p] = (f & 3) << 2;
    }
    // B staging: 4096 words/chunk, 4 cp per thread
    int bkp[4], bn4[4];
#pragma unroll
    for (int p = 0; p < 4; ++p) {
        int f = tid + p * 256;
        bkp[p] = f >> 6;                 // 0..15
        bn4[p] = (f & 63) << 2;          // 0..252
    }

    auto issue = [&](int it) {
        const int tap = it >> 5;
        const int kp0 = (it & 31) << 4;  // word offset of chunk in row
        const uint32_t sb = smb + (uint32_t)(it % 3) * STG_BYTES;
        const uint32_t* wt = Wc + (size_t)tap * HW * HH;
#pragma unroll
        for (int p = 0; p < 2; ++p) {
            int srow = tb + am[p] + tap - CENTER;
            uint32_t sz = 16;
            int sr = srow;
            if (TAPS > 1) {
                sz = (srow >= 0 && srow < SS) ? 16u : 0u;
                sr = srow < 0 ? 0 : (srow >= SS ? SS - 1 : srow);
            }
            const uint32_t* srcA = Xc + ((size_t)batch * SS + sr) * HW + kp0 + ac4[p];
            CP_ASYNC(sb + (uint32_t)(am[p] * A_STRIDE + ac4[p]) * 4, srcA, sz);
        }
#pragma unroll
        for (int p = 0; p < 4; ++p) {
            const uint32_t* srcB = wt + (size_t)(kp0 + bkp[p]) * HH + n0 + bn4[p];
            uint32_t swz = (uint32_t)(bn4[p] ^ ((bkp[p] & 3) << 3));
            CP_ASYNC(sb + (A_WORDS + (uint32_t)bkp[p] * 256 + swz) * 4, srcB, 16u);
        }
    };

    float acc[4][8][4];
#pragma unroll
    for (int i = 0; i < 4; ++i)
#pragma unroll
        for (int j = 0; j < 8; ++j)
#pragma unroll
            for (int r = 0; r < 4; ++r) acc[i][j][r] = 0.f;

    issue(0); CP_COMMIT();
    issue(1); CP_COMMIT();

    for (int it = 0; it < NIT; ++it) {
        CP_WAIT1();
        __syncthreads();
        if (it + 2 < NIT) issue(it + 2);
        CP_COMMIT();

        const uint32_t* sA = sm + (it % 3) * STG_WORDS;
        const uint32_t* sB = sA + A_WORDS;
#pragma unroll
        for (int s = 0; s < 2; ++s) {
            const int kp1 = s * 8 + tg;
            const int kp2 = kp1 + 4;
            uint32_t a[4][4], b[8][2];
#pragma unroll
            for (int mt = 0; mt < 4; ++mt) {
                int mr = wm * 64 + mt * 16 + g;
                a[mt][0] = sA[mr * A_STRIDE + kp1];
                a[mt][1] = sA[(mr + 8) * A_STRIDE + kp1];
                a[mt][2] = sA[mr * A_STRIDE + kp2];
                a[mt][3] = sA[(mr + 8) * A_STRIDE + kp2];
            }
#pragma unroll
            for (int nt = 0; nt < 8; ++nt) {
                int ncx = (wn * 64 + nt * 8 + g) ^ (tg << 3);
                b[nt][0] = sB[kp1 * 256 + ncx];
                b[nt][1] = sB[kp2 * 256 + ncx];
            }
#pragma unroll
            for (int mt = 0; mt < 4; ++mt)
#pragma unroll
                for (int nt = 0; nt < 8; ++nt)
                    mma_f16(acc[mt][nt], a[mt], b[nt]);
        }
    }

#pragma unroll
    for (int mt = 0; mt < 4; ++mt)
#pragma unroll
        for (int half = 0; half < 2; ++half) {
            int m = m0 + wm * 64 + mt * 16 + g + half * 8;
            int bidx = m >> 11;
            int t = m & (SS - 1);
#pragma unroll
            for (int nt = 0; nt < 8; ++nt) {
                int n = n0 + wn * 64 + nt * 8 + tg * 2;
                float ox = (acc[mt][nt][half * 2 + 0] + bias[n + 0]) * scale;
                float oy = (acc[mt][nt][half * 2 + 1] + bias[n + 1]) * scale;
                if (HEADS_OUT) {
                    int h = n >> 6;
                    int dp = (n & 63) >> 1;
                    ((uint32_t*)Yv_)[(((size_t)bidx * NH + h) * SS + t) * (DD / 2) + dp] =
                        pack_h2(ox, oy);
                } else {
                    *(float2*)((float*)Yv_ + (size_t)m * HH + n) = make_float2(ox, oy);
                }
            }
        }
}

__global__ __launch_bounds__(256, 1) void conv3_ca(
    const uint32_t* __restrict__ Xq, const uint32_t* __restrict__ Xs,
    const uint32_t* __restrict__ Wc,
    const float* __restrict__ bq, const float* __restrict__ bk,
    const float* __restrict__ bv,
    uint32_t* __restrict__ Yq, uint32_t* __restrict__ Yk,
    uint32_t* __restrict__ Yv)
{
    const int z = blockIdx.z;
    gemm_ca_core<3, true>(z ? Xs : Xq, Wc + (size_t)z * 3 * HW * HH,
                          z == 0 ? bq : (z == 1 ? bk : bv),
                          z == 0 ? Yq : (z == 1 ? Yk : Yv),
                          z == 0 ? 0.125f : 1.0f,
                          blockIdx.y * 128, blockIdx.x * 256);
}

__global__ __launch_bounds__(256, 1) void outproj_ca(
    const uint32_t* __restrict__ Xc, const uint32_t* __restrict__ Wc,
    const float* __restrict__ bias, float* __restrict__ Y)
{
    gemm_ca_core<1, false>(Xc, Wc + (size_t)9 * HW * HH, bias, Y, 1.0f,
                           blockIdx.y * 128, blockIdx.x * 256);
}

// ---------------------------------------------------------------------------
// Attention v4 (fp16 m16n8k16): S C-fragment IS the PV A-fragment (packed),
// no shuffles, no permutation. K staged [key][dp], Vt staged [d][keyp].
// cp.async 4-buffer pipeline, ONE sync per key tile.
// ---------------------------------------------------------------------------
#define KN_W (64 * 36)                   // 2304
#define VT_W (64 * 36)                   // 2304
#define BUF_W (KN_W + VT_W)              // 4608
#define MSK_OFF (4 * BUF_W)              // 18432
#define ATTN_DSMEM ((MSK_OFF + SS) * 4)  // 81920 bytes

__global__ __launch_bounds__(256, 1) void attn_tc(const float* __restrict__ mask,
                                                  uint32_t* __restrict__ Aout)
{
    extern __shared__ uint32_t sm[];
    const uint32_t smb = smem_u32(sm);
    float* msk = (float*)(sm + MSK_OFF);

    const int q0 = blockIdx.x * 128;
    const int h = blockIdx.y;
    const int b = blockIdx.z;
    const int tid = threadIdx.x;
    const int wid = tid >> 5;
    const int lane = tid & 31;
    const int g = lane >> 2;
    const int tg = lane & 3;
    const int bh = b * NH + h;
    const size_t basew = (size_t)bh * SS * (DD / 2);
    const int qr = q0 + wid * 16;

    for (int i = tid; i < SS; i += 256)
        msk[i] = mask[(size_t)b * SS + i] * (-1e9f);

    // Q A-fragments (4 k16 steps over D=64), packed words
    uint32_t qa[4][4];
    {
        const uint32_t* Qp = g_Q + basew + (size_t)(qr + g) * (DD / 2);
#pragma unroll
        for (int s = 0; s < 4; ++s) {
            qa[s][0] = Qp[8 * s + tg];
            qa[s][1] = Qp[8 * 32 + 8 * s + tg];        // row +8
            qa[s][2] = Qp[8 * s + tg + 4];
            qa[s][3] = Qp[8 * 32 + 8 * s + tg + 4];
        }
    }

    // staging coords: K 512 cp, Vt 512 cp -> 2+2 per thread
    int srow[2], sc4[2];
#pragma unroll
    for (int p = 0; p < 2; ++p) {
        int f = tid + p * 256;
        srow[p] = f >> 3;
        sc4[p] = (f & 7) << 2;
    }
    const uint32_t* Vtg = g_Vt + (size_t)bh * DD * (SS / 2);

    auto stage = [&](int t) {
        const int buf = t & 3;
        const int k0 = t << 6;
#pragma unroll
        for (int p = 0; p < 2; ++p) {
            CP_ASYNC(smb + (uint32_t)(buf * BUF_W + srow[p] * 36 + sc4[p]) * 4,
                     g_K + basew + (size_t)(k0 + srow[p]) * (DD / 2) + sc4[p], 16u);
            CP_ASYNC(smb + (uint32_t)(buf * BUF_W + KN_W + srow[p] * 36 + sc4[p]) * 4,
                     Vtg + (size_t)srow[p] * (SS / 2) + (k0 >> 1) + sc4[p], 16u);
        }
    };

    float oacc[8][4];
#pragma unroll
    for (int nt = 0; nt < 8; ++nt)
#pragma unroll
        for (int r = 0; r < 4; ++r) oacc[nt][r] = 0.f;
    float m0 = -1e30f, m8 = -1e30f, l0 = 0.f, l8 = 0.f;

    stage(0); CP_COMMIT();
    stage(1); CP_COMMIT();

    for (int t = 0; t < 32; ++t) {
        if (t + 2 < 32) stage(t + 2);
        CP_COMMIT();
        CP_WAIT2();
        __syncthreads();

        const uint32_t* Kb = sm + (t & 3) * BUF_W;
        const uint32_t* Vb = Kb + KN_W;
        const int k0 = t << 6;

        // S = Q K^T : 4 k16 steps x 8 key fragments
        float sacc[8][4];
#pragma unroll
        for (int nt = 0; nt < 8; ++nt)
#pragma unroll
            for (int r = 0; r < 4; ++r) sacc[nt][r] = 0.f;
#pragma unroll
        for (int s = 0; s < 4; ++s)
#pragma unroll
            for (int nt = 0; nt < 8; ++nt) {
                uint32_t bfr[2];
                bfr[0] = Kb[(nt * 8 + g) * 36 + 8 * s + tg];
                bfr[1] = Kb[(nt * 8 + g) * 36 + 8 * s + tg + 4];
                mma_f16(sacc[nt], qa[s], bfr);
            }

        // additive mask (natural columns: 2tg, 2tg+1)
#pragma unroll
        for (int nt = 0; nt < 8; ++nt) {
            float mk0 = msk[k0 + nt * 8 + 2 * tg];
            float mk1 = msk[k0 + nt * 8 + 2 * tg + 1];
            sacc[nt][0] += mk0; sacc[nt][1] += mk1;
            sacc[nt][2] += mk0; sacc[nt][3] += mk1;
        }

        float r0 = -1e30f, r8 = -1e30f;
#pragma unroll
        for (int nt = 0; nt < 8; ++nt) {
            r0 = fmaxf(r0, fmaxf(sacc[nt][0], sacc[nt][1]));
            r8 = fmaxf(r8, fmaxf(sacc[nt][2], sacc[nt][3]));
        }
        r0 = fmaxf(r0, __shfl_xor_sync(0xffffffffu, r0, 1));
        r0 = fmaxf(r0, __shfl_xor_sync(0xffffffffu, r0, 2));
        r8 = fmaxf(r8, __shfl_xor_sync(0xffffffffu, r8, 1));
        r8 = fmaxf(r8, __shfl_xor_sync(0xffffffffu, r8, 2));

        float nm0 = fmaxf(m0, r0), nm8 = fmaxf(m8, r8);
        float cr0 = __expf(m0 - nm0), cr8 = __expf(m8 - nm8);

        float s0 = 0.f, s8 = 0.f;
#pragma unroll
        for (int nt = 0; nt < 8; ++nt) {
            sacc[nt][0] = __expf(sacc[nt][0] - nm0);
            sacc[nt][1] = __expf(sacc[nt][1] - nm0);
            sacc[nt][2] = __expf(sacc[nt][2] - nm8);
            sacc[nt][3] = __expf(sacc[nt][3] - nm8);
            s0 += sacc[nt][0] + sacc[nt][1];
            s8 += sacc[nt][2] + sacc[nt][3];
        }
        s0 += __shfl_xor_sync(0xffffffffu, s0, 1);
        s0 += __shfl_xor_sync(0xffffffffu, s0, 2);
        s8 += __shfl_xor_sync(0xffffffffu, s8, 1);
        s8 += __shfl_xor_sync(0xffffffffu, s8, 2);

        l0 = l0 * cr0 + s0;
        l8 = l8 * cr8 + s8;
        m0 = nm0; m8 = nm8;

#pragma unroll
        for (int nt = 0; nt < 8; ++nt) {
            oacc[nt][0] *= cr0; oacc[nt][1] *= cr0;
            oacc[nt][2] *= cr8; oacc[nt][3] *= cr8;
        }

        // O += P V : pack C-fragments straight into A-fragments (no shfl)
#pragma unroll
        for (int s = 0; s < 4; ++s) {
            uint32_t pa[4];
            pa[0] = pack_h2(sacc[2 * s][0], sacc[2 * s][1]);         // row g,  k 16s+2tg
            pa[1] = pack_h2(sacc[2 * s][2], sacc[2 * s][3]);         // row g+8
            pa[2] = pack_h2(sacc[2 * s + 1][0], sacc[2 * s + 1][1]); // row g,  k 16s+8+2tg
            pa[3] = pack_h2(sacc[2 * s + 1][2], sacc[2 * s + 1][3]); // row g+8
#pragma unroll
            for (int nt = 0; nt < 8; ++nt) {
                uint32_t bfr[2];
                bfr[0] = Vb[(nt * 8 + g) * 36 + 8 * s + tg];
                bfr[1] = Vb[(nt * 8 + g) * 36 + 8 * s + tg + 4];
                mma_f16(oacc[nt], pa, bfr);
            }
        }
    }

    const float inv0 = 1.f / l0, inv8 = 1.f / l8;
#pragma unroll
    for (int nt = 0; nt < 8; ++nt) {
        uint32_t w0 = pack_h2(oacc[nt][0] * inv0, oacc[nt][1] * inv0);
        uint32_t w8 = pack_h2(oacc[nt][2] * inv8, oacc[nt][3] * inv8);
        size_t col = (size_t)h * 32 + nt * 4 + tg;
        Aout[((size_t)b * SS + qr + g) * HW + col] = w0;
        Aout[((size_t)b * SS + qr + g + 8) * HW + col] = w8;
    }
}

// ---------------------------------------------------------------------------
extern "C" void kernel_launch(void* const* d_in, const int* in_sizes, int n_in,
                              void* d_out, int out_size)
{
    const float* qin  = (const float*)d_in[0];
    const float* src  = (const float*)d_in[1];
    const float* mask = (const float*)d_in[2];
    const float* Wq   = (const float*)d_in[3];
    const float* bq   = (const float*)d_in[4];
    const float* Wk   = (const float*)d_in[5];
    const float* bk   = (const float*)d_in[6];
    const float* Wv   = (const float*)d_in[7];
    const float* bv   = (const float*)d_in[8];
    const float* Wo   = (const float*)d_in[9];
    const float* bo   = (const float*)d_in[10];
    float* out = (float*)d_out;

    uint32_t *gQ, *gK, *gV, *gVt, *gAc, *gXq, *gXs, *gW;
    cudaGetSymbolAddress((void**)&gQ, g_Q);
    cudaGetSymbolAddress((void**)&gK, g_K);
    cudaGetSymbolAddress((void**)&gV, g_V);
    cudaGetSymbolAddress((void**)&gVt, g_Vt);
    cudaGetSymbolAddress((void**)&gAc, g_Ac);
    cudaGetSymbolAddress((void**)&gXq, g_Xqc);
    cudaGetSymbolAddress((void**)&gXs, g_Xsc);
    cudaGetSymbolAddress((void**)&gW, g_Wc);

    cudaFuncSetAttribute(conv3_ca, cudaFuncAttributeMaxDynamicSharedMemorySize,
                         GEMM_DSMEM);
    cudaFuncSetAttribute(outproj_ca, cudaFuncAttributeMaxDynamicSharedMemorySize,
                         GEMM_DSMEM);
    cudaFuncSetAttribute(attn_tc, cudaFuncAttributeMaxDynamicSharedMemorySize,
                         ATTN_DSMEM);

    const int N4 = BB * SS * HH / 4;
    cvt4<<<(N4 + 255) / 256, 256>>>(qin, gXq, N4);
    cvt4<<<(N4 + 255) / 256, 256>>>(src, gXs, N4);
    dim3 gridW(HW * HH / 256, 1, 10);             // (2048, 1, 10)
    cvt_w<<<gridW, 256>>>(Wq, Wk, Wv, Wo, gW);

    dim3 gridC(HH / 256, (BB * SS) / 128, 3);     // (4, 32, 3)
    conv3_ca<<<gridC, 256, GEMM_DSMEM>>>(gXq, gXs, gW, bq, bk, bv, gQ, gK, gV);

    dim3 gridR(SS / 64, BB * NH);                 // (32, 32)
    repack_v<<<gridR, 256>>>(gV, gVt);

    dim3 gridAttn(SS / 128, NH, BB);              // (16, 16, 2)
    attn_tc<<<gridAttn, 256, ATTN_DSMEM>>>(mask, gAc);

    dim3 gridO(HH / 256, (BB * SS) / 128);        // (4, 32)
    outproj_ca<<<gridO, 256, GEMM_DSMEM>>>(gAc, gW, bo, out);
}